// round 9
// baseline (speedup 1.0000x reference)
#include <cuda_runtime.h>
#include <math.h>
#include <stdint.h>

#define BB 4
#define TT 2048
#define HH 1024
#define NH 16
#define HD 64
#define H3 3072

// Scratch (allocation-free rule: __device__ globals)
__device__ float g_qkv[(size_t)BB * TT * H3];   // (B,T,3H)
__device__ float g_att[(size_t)BB * TT * HH];   // (B,T,H), tf32-rounded
__device__ float g_xr [(size_t)BB * TT * HH];   // input, tf32-rounded
__device__ float g_wqT[(size_t)H3 * HH];        // w_qkv^T (3H,H), tf32-rounded
__device__ float g_woT[(size_t)HH * HH];        // w_out^T (H,H), tf32-rounded
__device__ int   g_len[BB];

// ---------------------------------------------------------------------------
// helpers
// ---------------------------------------------------------------------------
__device__ __forceinline__ unsigned f2tf32(float f) {
    unsigned u;
    asm("cvt.rna.tf32.f32 %0, %1;" : "=r"(u) : "f"(f));
    return u;
}

__device__ __forceinline__ void mma_tf32(
    float* d, const unsigned* a, const unsigned* b)
{
    asm volatile(
        "mma.sync.aligned.m16n8k8.row.col.f32.tf32.tf32.f32 "
        "{%0,%1,%2,%3}, {%4,%5,%6,%7}, {%8,%9}, {%0,%1,%2,%3};\n"
        : "+f"(d[0]), "+f"(d[1]), "+f"(d[2]), "+f"(d[3])
        : "r"(a[0]), "r"(a[1]), "r"(a[2]), "r"(a[3]),
          "r"(b[0]), "r"(b[1]));
}

__device__ __forceinline__ uint32_t smem_u32(const void* p) {
    uint32_t a;
    asm("{ .reg .u64 t; cvta.to.shared.u64 t, %1; cvt.u32.u64 %0, t; }"
        : "=r"(a) : "l"(p));
    return a;
}

#define CP16(dst, src) \
    asm volatile("cp.async.ca.shared.global [%0], [%1], 16;" \
                 :: "r"(dst), "l"(src) : "memory")
#define CPCOMMIT() asm volatile("cp.async.commit_group;" ::: "memory")

#define LDSM4(r0, r1, r2, r3, addr) \
    asm volatile("ldmatrix.sync.aligned.m8n8.x4.shared.b16 {%0,%1,%2,%3}, [%4];" \
                 : "=r"(r0), "=r"(r1), "=r"(r2), "=r"(r3) : "r"(addr))

// SW128 swizzle on 16B granules within a 128B row
#define SWR(row, byteoff) (((row) * 128 + (byteoff)) ^ (((row) & 7) << 4))

// ---------------------------------------------------------------------------
// Per-batch valid-prefix length; mask dtype sniffed from first 4 bytes.
// ---------------------------------------------------------------------------
__global__ void len_kernel(const unsigned char* __restrict__ mask) {
    __shared__ int sred[256];
    const unsigned int w0 = *(const unsigned int*)mask;
    const int b = blockIdx.x;
    int cnt = 0;
    if (w0 == 0x01010101u) {
        for (int t = threadIdx.x; t < TT; t += 256)
            cnt += (mask[(size_t)b * TT + t] != 0) ? 1 : 0;
    } else if (w0 == 0x3F800000u) {
        const float* m = (const float*)mask;
        for (int t = threadIdx.x; t < TT; t += 256)
            cnt += (m[(size_t)b * TT + t] != 0.f) ? 1 : 0;
    } else {
        const int* m = (const int*)mask;
        for (int t = threadIdx.x; t < TT; t += 256)
            cnt += (m[(size_t)b * TT + t] != 0) ? 1 : 0;
    }
    sred[threadIdx.x] = cnt;
    __syncthreads();
    for (int s = 128; s > 0; s >>= 1) {
        if (threadIdx.x < s) sred[threadIdx.x] += sred[threadIdx.x + s];
        __syncthreads();
    }
    if (threadIdx.x == 0) g_len[b] = sred[0];
}

// ---------------------------------------------------------------------------
// Round fp32 array to tf32 (rna) in a scratch copy.
// ---------------------------------------------------------------------------
__global__ void cvt_pre(const float4* __restrict__ in, float4* __restrict__ out,
                        int n4)
{
    for (int i = blockIdx.x * blockDim.x + threadIdx.x; i < n4;
         i += gridDim.x * blockDim.x) {
        float4 v = in[i];
        float4 r = { __uint_as_float(f2tf32(v.x)), __uint_as_float(f2tf32(v.y)),
                     __uint_as_float(f2tf32(v.z)), __uint_as_float(f2tf32(v.w)) };
        out[i] = r;
    }
}

// ---------------------------------------------------------------------------
// Weight transpose + tf32 round: D(C,R) = round(S(R,C)^T)
// ---------------------------------------------------------------------------
__global__ void transpose_w(const float* __restrict__ S, float* __restrict__ D,
                            int R, int C)
{
    __shared__ float t[32][33];
    const int x = blockIdx.x * 32 + threadIdx.x;
    const int y0 = blockIdx.y * 32;
    #pragma unroll
    for (int i = threadIdx.y; i < 32; i += 8)
        t[i][threadIdx.x] = S[(size_t)(y0 + i) * C + x];
    __syncthreads();
    const int xo = y0 + threadIdx.x;
    const int yo0 = blockIdx.x * 32;
    #pragma unroll
    for (int i = threadIdx.y; i < 32; i += 8)
        D[(size_t)(yo0 + i) * R + xo] =
            __uint_as_float(f2tf32(t[threadIdx.x][i]));
}

// ---------------------------------------------------------------------------
// tf32 HMMA GEMM: CTA 128x256, 8 warps of 64x64, K-chunk 32, 3-stage cp.async,
// ONE sync per chunk.  C(M,N) = A(M,K) @ Bt(N,K)^T + bias(N).
// Smem: A stages [128][32]f (16KB), B stages [256][32]f (32KB), 3 each =144KB.
// ---------------------------------------------------------------------------
#define TG_AST 16384
#define TG_BST 32768
#define TG_SMEM (3 * (TG_AST + TG_BST))

__global__ __launch_bounds__(256, 1) void tgemm_ldsm(
    const float* __restrict__ A, const float* __restrict__ Bt,
    const float* __restrict__ bias, float* __restrict__ C,
    int M, int N, int K)
{
    extern __shared__ char smem[];
    const uint32_t base = smem_u32(smem);

    const int tid   = threadIdx.x;
    const int warp  = tid >> 5;
    const int lane  = tid & 31;
    const int g     = lane >> 2;
    const int t     = lane & 3;
    const int warpM = warp & 1;        // 2 x 64 rows
    const int warpN = warp >> 1;       // 4 x 64 cols
    const int brow  = blockIdx.y * 128;
    const int bcol  = blockIdx.x * 256;

    // ---- loaders ----
    // A: row tid/2 (0..127), granules (tid&1)*4 .. +3
    const int arl = tid >> 1;
    const int agr = (tid & 1) * 4;
    const float* Ap = A + (size_t)(brow + arl) * K + agr * 4;
    // B: row tid (0..255), granules 0..7
    const float* Bp = Bt + (size_t)(bcol + tid) * K;

    // ---- consumer LDSM lane addressing (R8-proven) ----
    const int arow   = (lane & 7) + ((lane >> 3) & 1) * 8;
    const int acol   = (lane >> 4) * 16;
    const int brow_i = (lane & 7) + (lane >> 4) * 8;
    const int bcol_i = ((lane >> 3) & 1) * 16;

    float acc[4][8][4];
    #pragma unroll
    for (int i = 0; i < 4; i++)
        #pragma unroll
        for (int j = 0; j < 8; j++)
            #pragma unroll
            for (int q = 0; q < 4; q++) acc[i][j][q] = 0.f;

    const int nch = K >> 5;

    // stage smem bases
    uint32_t sA[3], sB[3];
    #pragma unroll
    for (int s = 0; s < 3; s++) {
        sA[s] = base + s * TG_AST;
        sB[s] = base + 3 * TG_AST + s * TG_BST;
    }

    // prologue: chunks 0,1 -> stages 0,1
    #pragma unroll
    for (int pc = 0; pc < 2; pc++) {
        #pragma unroll
        for (int q = 0; q < 4; q++)
            CP16(sA[pc] + SWR(arl, (agr + q) * 16), Ap + pc * 32 + q * 4);
        #pragma unroll
        for (int q = 0; q < 8; q++)
            CP16(sB[pc] + SWR(tid, q * 16), Bp + pc * 32 + q * 4);
        CPCOMMIT();
    }

    int st = 0, sp = 2;   // compute stage, prefetch stage
    for (int kc = 0; kc < nch; kc++) {
        if (kc < nch - 1)
            asm volatile("cp.async.wait_group 1;" ::: "memory");
        else
            asm volatile("cp.async.wait_group 0;" ::: "memory");
        __syncthreads();

        // prefetch chunk kc+2 into stage sp (reads of sp finished in iter
        // kc-1; the sync above orders them before these writes)
        if (kc + 2 < nch) {
            const float* Ap2 = Ap + (kc + 2) * 32;
            const float* Bp2 = Bp + (kc + 2) * 32;
            #pragma unroll
            for (int q = 0; q < 4; q++)
                CP16(sA[sp] + SWR(arl, (agr + q) * 16), Ap2 + q * 4);
            #pragma unroll
            for (int q = 0; q < 8; q++)
                CP16(sB[sp] + SWR(tid, q * 16), Bp2 + q * 4);
            CPCOMMIT();
        }

        const uint32_t aBase = sA[st];
        const uint32_t bBase = sB[st];

        #pragma unroll
        for (int ks = 0; ks < 4; ks++) {
            const int kb = ks * 32;
            unsigned af[4][4];
            #pragma unroll
            for (int mt = 0; mt < 4; mt++) {
                const int r = warpM * 64 + mt * 16 + arow;
                LDSM4(af[mt][0], af[mt][1], af[mt][2], af[mt][3],
                      aBase + SWR(r, kb + acol));
            }
            unsigned bf[8][2];
            #pragma unroll
            for (int np = 0; np < 4; np++) {
                const int r = warpN * 64 + np * 16 + brow_i;
                unsigned r0, r1, r2, r3;
                LDSM4(r0, r1, r2, r3, bBase + SWR(r, kb + bcol_i));
                bf[np * 2][0] = r0;      bf[np * 2][1] = r1;
                bf[np * 2 + 1][0] = r2;  bf[np * 2 + 1][1] = r3;
            }
            #pragma unroll
            for (int mt = 0; mt < 4; mt++)
                #pragma unroll
                for (int nt = 0; nt < 8; nt++)
                    mma_tf32(acc[mt][nt], af[mt], bf[nt]);
        }

        st = (st == 2) ? 0 : st + 1;
        sp = (sp == 2) ? 0 : sp + 1;
    }

    // epilogue: bias + store
    #pragma unroll
    for (int mt = 0; mt < 4; mt++) {
        const int r0 = brow + warpM * 64 + mt * 16 + g;
        #pragma unroll
        for (int nt = 0; nt < 8; nt++) {
            const int c = bcol + warpN * 64 + nt * 8 + 2 * t;
            const float bv0 = bias[c], bv1 = bias[c + 1];
            float2 v0 = {acc[mt][nt][0] + bv0, acc[mt][nt][1] + bv1};
            float2 v1 = {acc[mt][nt][2] + bv0, acc[mt][nt][3] + bv1};
            *(float2*)&C[(size_t)r0 * N + c]       = v0;
            *(float2*)&C[(size_t)(r0 + 8) * N + c] = v1;
        }
    }
}

// ---------------------------------------------------------------------------
// Flash attention with tf32 MMA; K/V tiles register-prefetched one kt ahead.
// (unchanged — proven)
// ---------------------------------------------------------------------------
__global__ __launch_bounds__(256) void attn_mma(
    const float* __restrict__ qkv, float* __restrict__ att)
{
    extern __shared__ unsigned smu[];
    unsigned* Qs = smu;
    unsigned* Ks = smu + 64 * 68;
    unsigned* Vs = smu + 2 * 64 * 68;
    float*    Ps = (float*)(smu + 3 * 64 * 68);
    float*    m_s = Ps + 64 * 68;
    float*    l_s = m_s + 64;
    float*    a_s = l_s + 64;

    const int tid  = threadIdx.x;
    const int warp = tid >> 5;
    const int lane = tid & 31;
    const int g = lane >> 2;
    const int t = lane & 3;
    const int wm = warp >> 1;
    const int wn = warp & 1;
    const int qt = blockIdx.x;
    const int b  = blockIdx.y >> 4;
    const int h  = blockIdx.y & 15;
    const int len = g_len[b];

    const float* qb = qkv + (size_t)b * TT * H3 + h * HD;
    const float* kb = qb + HH;
    const float* vb = qb + 2 * HH;

    const int rr = tid >> 4;
    const int d0 = (tid & 15) * 4;

    #pragma unroll
    for (int it = 0; it < 4; it++) {
        const int r = rr + it * 16;
        float4 q4 = *(const float4*)(qb + (size_t)(qt * 64 + r) * H3 + d0);
        Qs[r * 68 + d0 + 0] = f2tf32(q4.x);
        Qs[r * 68 + d0 + 1] = f2tf32(q4.y);
        Qs[r * 68 + d0 + 2] = f2tf32(q4.z);
        Qs[r * 68 + d0 + 3] = f2tf32(q4.w);
    }
    if (tid < 64) { m_s[tid] = -1e30f; l_s[tid] = 0.f; }

    float o[4][4];
    #pragma unroll
    for (int nt = 0; nt < 4; nt++)
        #pragma unroll
        for (int q = 0; q < 4; q++) o[nt][q] = 0.f;

    const int kt_max = min(qt, (len - 1) >> 6);

    float4 kreg[4], vreg[4];
    #pragma unroll
    for (int it = 0; it < 4; it++) {
        const int c = rr + it * 16;
        kreg[it] = *(const float4*)(kb + (size_t)c * H3 + d0);
        vreg[it] = *(const float4*)(vb + (size_t)c * H3 + d0);
    }
    __syncthreads();

    for (int kt = 0; kt <= kt_max; kt++) {
        #pragma unroll
        for (int it = 0; it < 4; it++) {
            const int c = rr + it * 16;
            Ks[c * 68 + d0 + 0] = f2tf32(kreg[it].x);
            Ks[c * 68 + d0 + 1] = f2tf32(kreg[it].y);
            Ks[c * 68 + d0 + 2] = f2tf32(kreg[it].z);
            Ks[c * 68 + d0 + 3] = f2tf32(kreg[it].w);
            Vs[c * 68 + d0 + 0] = f2tf32(vreg[it].x);
            Vs[c * 68 + d0 + 1] = f2tf32(vreg[it].y);
            Vs[c * 68 + d0 + 2] = f2tf32(vreg[it].z);
            Vs[c * 68 + d0 + 3] = f2tf32(vreg[it].w);
        }
        __syncthreads();

        if (kt < kt_max) {
            #pragma unroll
            for (int it = 0; it < 4; it++) {
                const int c = (kt + 1) * 64 + rr + it * 16;
                kreg[it] = *(const float4*)(kb + (size_t)c * H3 + d0);
                vreg[it] = *(const float4*)(vb + (size_t)c * H3 + d0);
            }
        }

        float s[4][4];
        #pragma unroll
        for (int nt = 0; nt < 4; nt++)
            #pragma unroll
            for (int q = 0; q < 4; q++) s[nt][q] = 0.f;

        #pragma unroll
        for (int k0 = 0; k0 < 64; k0 += 8) {
            unsigned af[4];
            const int r0 = wm * 16;
            af[0] = Qs[(r0 + g) * 68 + k0 + t];
            af[1] = Qs[(r0 + g + 8) * 68 + k0 + t];
            af[2] = Qs[(r0 + g) * 68 + k0 + t + 4];
            af[3] = Qs[(r0 + g + 8) * 68 + k0 + t + 4];
            #pragma unroll
            for (int nt = 0; nt < 4; nt++) {
                const int c = wn * 32 + nt * 8 + g;
                unsigned bf[2] = { Ks[c * 68 + k0 + t], Ks[c * 68 + k0 + t + 4] };
                mma_tf32(s[nt], af, bf);
            }
        }

        {
            const int r0 = wm * 16 + g;
            const int q0 = qt * 64;
            #pragma unroll
            for (int nt = 0; nt < 4; nt++) {
                const int c0 = wn * 32 + nt * 8 + 2 * t;
                const int kc = kt * 64 + c0;
                Ps[r0 * 68 + c0] =
                    (kc <= q0 + r0 && kc < len) ? s[nt][0] * 0.125f : -1e30f;
                Ps[r0 * 68 + c0 + 1] =
                    (kc + 1 <= q0 + r0 && kc + 1 < len) ? s[nt][1] * 0.125f : -1e30f;
                Ps[(r0 + 8) * 68 + c0] =
                    (kc <= q0 + r0 + 8 && kc < len) ? s[nt][2] * 0.125f : -1e30f;
                Ps[(r0 + 8) * 68 + c0 + 1] =
                    (kc + 1 <= q0 + r0 + 8 && kc + 1 < len) ? s[nt][3] * 0.125f : -1e30f;
            }
        }
        __syncthreads();

        {
            const int r = tid >> 2, qq = tid & 3;
            float* prow = Ps + r * 68 + qq * 16;
            float mx = -1e30f;
            #pragma unroll
            for (int c = 0; c < 16; c++) mx = fmaxf(mx, prow[c]);
            mx = fmaxf(mx, __shfl_xor_sync(0xffffffffu, mx, 1));
            mx = fmaxf(mx, __shfl_xor_sync(0xffffffffu, mx, 2));
            const float mo = m_s[r];
            const float mn = fmaxf(mo, mx);
            float sum = 0.f;
            #pragma unroll
            for (int c = 0; c < 16; c++) {
                float e = __expf(prow[c] - mn);
                prow[c] = __uint_as_float(f2tf32(e));
                sum += e;
            }
            sum += __shfl_xor_sync(0xffffffffu, sum, 1);
            sum += __shfl_xor_sync(0xffffffffu, sum, 2);
            if (qq == 0) {
                float a = __expf(mo - mn);
                a_s[r] = a;
                l_s[r] = l_s[r] * a + sum;
                m_s[r] = mn;
            }
        }
        __syncthreads();

        {
            const float a0 = a_s[wm * 16 + g];
            const float a1 = a_s[wm * 16 + g + 8];
            #pragma unroll
            for (int nt = 0; nt < 4; nt++) {
                o[nt][0] *= a0; o[nt][1] *= a0;
                o[nt][2] *= a1; o[nt][3] *= a1;
            }
        }

        {
            const unsigned* Pu = (const unsigned*)Ps;
            #pragma unroll
            for (int k0 = 0; k0 < 64; k0 += 8) {
                unsigned af[4];
                const int r0 = wm * 16;
                af[0] = Pu[(r0 + g) * 68 + k0 + t];
                af[1] = Pu[(r0 + g + 8) * 68 + k0 + t];
                af[2] = Pu[(r0 + g) * 68 + k0 + t + 4];
                af[3] = Pu[(r0 + g + 8) * 68 + k0 + t + 4];
                #pragma unroll
                for (int nt = 0; nt < 4; nt++) {
                    const int c = wn * 32 + nt * 8 + g;
                    unsigned bf[2] = { Vs[(k0 + t) * 68 + c],
                                       Vs[(k0 + t + 4) * 68 + c] };
                    mma_tf32(o[nt], af, bf);
                }
            }
        }
        __syncthreads();
    }

    {
        const int r0 = wm * 16 + g;
        const float inv0 = 1.f / l_s[r0];
        const float inv1 = 1.f / l_s[r0 + 8];
        float* ob = att + (size_t)b * TT * HH + (size_t)(qt * 64) * HH + h * HD;
        #pragma unroll
        for (int nt = 0; nt < 4; nt++) {
            const int c = wn * 32 + nt * 8 + 2 * t;
            float2 v0 = { __uint_as_float(f2tf32(o[nt][0] * inv0)),
                          __uint_as_float(f2tf32(o[nt][1] * inv0)) };
            float2 v1 = { __uint_as_float(f2tf32(o[nt][2] * inv1)),
                          __uint_as_float(f2tf32(o[nt][3] * inv1)) };
            *(float2*)&ob[(size_t)r0 * HH + c]       = v0;
            *(float2*)&ob[(size_t)(r0 + 8) * HH + c] = v1;
        }
    }
}

// ---------------------------------------------------------------------------

static const int ATTN_SMEM = (4 * 64 * 68 + 3 * 64) * 4;  // 70400 B

extern "C" void kernel_launch(void* const* d_in, const int* in_sizes, int n_in,
                              void* d_out, int out_size)
{
    const float*         inp   = (const float*)d_in[0];
    const unsigned char* mask  = (const unsigned char*)d_in[1];
    const float*         w_qkv = (const float*)d_in[2];
    const float*         b_qkv = (const float*)d_in[3];
    const float*         w_out = (const float*)d_in[4];
    const float*         b_out = (const float*)d_in[5];
    float*               out   = (float*)d_out;

    float *qkv_p, *att_p, *xr_p, *wqT_p, *woT_p;
    cudaGetSymbolAddress((void**)&qkv_p, g_qkv);
    cudaGetSymbolAddress((void**)&att_p, g_att);
    cudaGetSymbolAddress((void**)&xr_p,  g_xr);
    cudaGetSymbolAddress((void**)&wqT_p, g_wqT);
    cudaGetSymbolAddress((void**)&woT_p, g_woT);

    cudaFuncSetAttribute(attn_mma,
                         cudaFuncAttributeMaxDynamicSharedMemorySize, ATTN_SMEM);
    cudaFuncSetAttribute(tgemm_ldsm,
                         cudaFuncAttributeMaxDynamicSharedMemorySize, TG_SMEM);

    len_kernel<<<BB, 256>>>(mask);
    cvt_pre<<<512, 256>>>((const float4*)inp, (float4*)xr_p,
                          (BB * TT * HH) / 4);
    transpose_w<<<dim3(H3 / 32, HH / 32), dim3(32, 8)>>>(w_qkv, wqT_p, HH, H3);
    transpose_w<<<dim3(HH / 32, HH / 32), dim3(32, 8)>>>(w_out, woT_p, HH, HH);

    tgemm_ldsm<<<dim3(H3 / 256, (BB * TT) / 128), 256, TG_SMEM>>>(
        xr_p, wqT_p, b_qkv, qkv_p, BB * TT, H3, HH);
    attn_mma<<<dim3(TT / 64, BB * NH), 256, ATTN_SMEM>>>(qkv_p, att_p);
    tgemm_ldsm<<<dim3(HH / 256, (BB * TT) / 128), 256, TG_SMEM>>>(
        att_p, woT_p, b_out, out, BB * TT, HH, HH);
}

// round 10
// speedup vs baseline: 1.3288x; 1.3288x over previous
#include <cuda_runtime.h>
#include <math.h>
#include <stdint.h>

#define BB 4
#define TT 2048
#define HH 1024
#define NH 16
#define HD 64
#define H3 3072

// Scratch (allocation-free rule: __device__ globals)
__device__ float g_qkv[(size_t)BB * TT * H3];   // (B,T,3H)
__device__ float g_att[(size_t)BB * TT * HH];   // (B,T,H), tf32-rounded
__device__ float g_xr [(size_t)BB * TT * HH];   // input, tf32-rounded
__device__ float g_wqT[(size_t)H3 * HH];        // w_qkv^T (3H,H), tf32-rounded
__device__ float g_woT[(size_t)HH * HH];        // w_out^T (H,H), tf32-rounded
__device__ int   g_len[BB];

// ---------------------------------------------------------------------------
// helpers
// ---------------------------------------------------------------------------
__device__ __forceinline__ unsigned f2tf32(float f) {
    unsigned u;
    asm("cvt.rna.tf32.f32 %0, %1;" : "=r"(u) : "f"(f));
    return u;
}

__device__ __forceinline__ void mma_tf32(
    float* d, const unsigned* a, const unsigned* b)
{
    asm volatile(
        "mma.sync.aligned.m16n8k8.row.col.f32.tf32.tf32.f32 "
        "{%0,%1,%2,%3}, {%4,%5,%6,%7}, {%8,%9}, {%0,%1,%2,%3};\n"
        : "+f"(d[0]), "+f"(d[1]), "+f"(d[2]), "+f"(d[3])
        : "r"(a[0]), "r"(a[1]), "r"(a[2]), "r"(a[3]),
          "r"(b[0]), "r"(b[1]));
}

__device__ __forceinline__ uint32_t smem_u32(const void* p) {
    uint32_t a;
    asm("{ .reg .u64 t; cvta.to.shared.u64 t, %1; cvt.u32.u64 %0, t; }"
        : "=r"(a) : "l"(p));
    return a;
}

#define CP16(dst, src) \
    asm volatile("cp.async.ca.shared.global [%0], [%1], 16;" \
                 :: "r"(dst), "l"(src) : "memory")
#define CPCOMMIT() asm volatile("cp.async.commit_group;" ::: "memory")

#define LDSM4(r0, r1, r2, r3, addr) \
    asm volatile("ldmatrix.sync.aligned.m8n8.x4.shared.b16 {%0,%1,%2,%3}, [%4];" \
                 : "=r"(r0), "=r"(r1), "=r"(r2), "=r"(r3) : "r"(addr))

// SW128 swizzle on 16B granules within a 128B row
#define SWR(row, byteoff) (((row) * 128 + (byteoff)) ^ (((row) & 7) << 4))

// ---------------------------------------------------------------------------
// Per-batch valid-prefix length; mask dtype sniffed from first 4 bytes.
// ---------------------------------------------------------------------------
__global__ void len_kernel(const unsigned char* __restrict__ mask) {
    __shared__ int sred[256];
    const unsigned int w0 = *(const unsigned int*)mask;
    const int b = blockIdx.x;
    int cnt = 0;
    if (w0 == 0x01010101u) {
        for (int t = threadIdx.x; t < TT; t += 256)
            cnt += (mask[(size_t)b * TT + t] != 0) ? 1 : 0;
    } else if (w0 == 0x3F800000u) {
        const float* m = (const float*)mask;
        for (int t = threadIdx.x; t < TT; t += 256)
            cnt += (m[(size_t)b * TT + t] != 0.f) ? 1 : 0;
    } else {
        const int* m = (const int*)mask;
        for (int t = threadIdx.x; t < TT; t += 256)
            cnt += (m[(size_t)b * TT + t] != 0) ? 1 : 0;
    }
    sred[threadIdx.x] = cnt;
    __syncthreads();
    for (int s = 128; s > 0; s >>= 1) {
        if (threadIdx.x < s) sred[threadIdx.x] += sred[threadIdx.x + s];
        __syncthreads();
    }
    if (threadIdx.x == 0) g_len[b] = sred[0];
}

// ---------------------------------------------------------------------------
// Round fp32 array to tf32 (rna) in a scratch copy.
// ---------------------------------------------------------------------------
__global__ void cvt_pre(const float4* __restrict__ in, float4* __restrict__ out,
                        int n4)
{
    for (int i = blockIdx.x * blockDim.x + threadIdx.x; i < n4;
         i += gridDim.x * blockDim.x) {
        float4 v = in[i];
        float4 r = { __uint_as_float(f2tf32(v.x)), __uint_as_float(f2tf32(v.y)),
                     __uint_as_float(f2tf32(v.z)), __uint_as_float(f2tf32(v.w)) };
        out[i] = r;
    }
}

// ---------------------------------------------------------------------------
// Weight transpose + tf32 round: D(C,R) = round(S(R,C)^T)
// ---------------------------------------------------------------------------
__global__ void transpose_w(const float* __restrict__ S, float* __restrict__ D,
                            int R, int C)
{
    __shared__ float t[32][33];
    const int x = blockIdx.x * 32 + threadIdx.x;
    const int y0 = blockIdx.y * 32;
    #pragma unroll
    for (int i = threadIdx.y; i < 32; i += 8)
        t[i][threadIdx.x] = S[(size_t)(y0 + i) * C + x];
    __syncthreads();
    const int xo = y0 + threadIdx.x;
    const int yo0 = blockIdx.x * 32;
    #pragma unroll
    for (int i = threadIdx.y; i < 32; i += 8)
        D[(size_t)(yo0 + i) * R + xo] =
            __uint_as_float(f2tf32(t[threadIdx.x][i]));
}

// ---------------------------------------------------------------------------
// tf32 HMMA GEMM (exact R8 revert): cp.async + SW128 swizzle + ldmatrix.
// CTA 128x128, K-chunk 32, 2 stages, 8 warps (2x4), warp tile 64x32.
// ---------------------------------------------------------------------------
#define TG_STAGE 16384
#define TG_SMEM  (4 * TG_STAGE)   // A0 A1 B0 B1

__global__ __launch_bounds__(256) void tgemm_ldsm(
    const float* __restrict__ A, const float* __restrict__ Bt,
    const float* __restrict__ bias, float* __restrict__ C,
    int M, int N, int K)
{
    extern __shared__ char smem[];
    const uint32_t sA0 = smem_u32(smem);
    const uint32_t sB0 = sA0 + 2 * TG_STAGE;

    const int tid   = threadIdx.x;
    const int warp  = tid >> 5;
    const int lane  = tid & 31;
    const int g     = lane >> 2;
    const int t     = lane & 3;
    const int warpM = warp & 1;
    const int warpN = warp >> 1;
    const int brow  = blockIdx.y * 128;
    const int bcol  = blockIdx.x * 128;

    const int lrow = tid >> 1;
    const int lg   = (tid & 1) * 4;
    const float* Ap = A  + (size_t)(brow + lrow) * K + lg * 4;
    const float* Bp = Bt + (size_t)(bcol + lrow) * K + lg * 4;
    uint32_t stA[2][4], stB[2][4];
    #pragma unroll
    for (int q = 0; q < 4; q++) {
        const uint32_t sw = SWR(lrow, (lg + q) * 16);
        stA[0][q] = sA0 + sw;
        stA[1][q] = sA0 + TG_STAGE + sw;
        stB[0][q] = sB0 + sw;
        stB[1][q] = sB0 + TG_STAGE + sw;
    }

    const int arow   = (lane & 7) + ((lane >> 3) & 1) * 8;
    const int acol   = (lane >> 4) * 16;
    const int brow_i = (lane & 7) + (lane >> 4) * 8;
    const int bcol_i = ((lane >> 3) & 1) * 16;

    float acc[4][4][4];
    #pragma unroll
    for (int i = 0; i < 4; i++)
        #pragma unroll
        for (int j = 0; j < 4; j++)
            #pragma unroll
            for (int q = 0; q < 4; q++) acc[i][j][q] = 0.f;

    const int nch = K >> 5;

    #pragma unroll
    for (int q = 0; q < 4; q++) {
        CP16(stA[0][q], Ap + q * 4);
        CP16(stB[0][q], Bp + q * 4);
    }
    CPCOMMIT();

    for (int kc = 0; kc < nch; kc++) {
        const int st = kc & 1;

        if (kc + 1 < nch) {
            const int sn = st ^ 1;
            const float* Ap2 = Ap + (kc + 1) * 32;
            const float* Bp2 = Bp + (kc + 1) * 32;
            #pragma unroll
            for (int q = 0; q < 4; q++) {
                CP16(stA[sn][q], Ap2 + q * 4);
                CP16(stB[sn][q], Bp2 + q * 4);
            }
            CPCOMMIT();
            asm volatile("cp.async.wait_group 1;" ::: "memory");
        } else {
            asm volatile("cp.async.wait_group 0;" ::: "memory");
        }
        __syncthreads();

        const uint32_t aBase = sA0 + st * TG_STAGE;
        const uint32_t bBase = sB0 + st * TG_STAGE;

        #pragma unroll
        for (int ks = 0; ks < 4; ks++) {
            const int kb = ks * 32;
            unsigned af[4][4];
            #pragma unroll
            for (int mt = 0; mt < 4; mt++) {
                const int r = warpM * 64 + mt * 16 + arow;
                LDSM4(af[mt][0], af[mt][1], af[mt][2], af[mt][3],
                      aBase + SWR(r, kb + acol));
            }
            unsigned bf[4][2];
            #pragma unroll
            for (int np = 0; np < 2; np++) {
                const int r = warpN * 32 + np * 16 + brow_i;
                unsigned r0, r1, r2, r3;
                LDSM4(r0, r1, r2, r3, bBase + SWR(r, kb + bcol_i));
                bf[np * 2][0] = r0;      bf[np * 2][1] = r1;
                bf[np * 2 + 1][0] = r2;  bf[np * 2 + 1][1] = r3;
            }
            #pragma unroll
            for (int mt = 0; mt < 4; mt++)
                #pragma unroll
                for (int nt = 0; nt < 4; nt++)
                    mma_tf32(acc[mt][nt], af[mt], bf[nt]);
        }
        __syncthreads();
    }

    #pragma unroll
    for (int mt = 0; mt < 4; mt++) {
        const int r0 = brow + warpM * 64 + mt * 16 + g;
        #pragma unroll
        for (int nt = 0; nt < 4; nt++) {
            const int c = bcol + warpN * 32 + nt * 8 + 2 * t;
            const float bv0 = bias[c], bv1 = bias[c + 1];
            float2 v0 = {acc[mt][nt][0] + bv0, acc[mt][nt][1] + bv1};
            float2 v1 = {acc[mt][nt][2] + bv0, acc[mt][nt][3] + bv1};
            *(float2*)&C[(size_t)r0 * N + c]       = v0;
            *(float2*)&C[(size_t)(r0 + 8) * N + c] = v1;
        }
    }
}

// ---------------------------------------------------------------------------
// FA2-style attention: CTA = 128 q-rows x (b,h); warp owns 16 rows end-to-end.
// Q frags resident in regs; K/V double-buffered (1 sync per kv-tile);
// softmax in registers (quad shuffles); P via warp-private smem + LDSM.
// Smem floats: K0 0, K1 4352, V0 8704, V1 13056, P 17408..26112 (104448 B).
// ---------------------------------------------------------------------------
#define AT_SMEM (26112 * 4)

__global__ __launch_bounds__(256) void attn_fa(
    const float* __restrict__ qkv, float* __restrict__ att)
{
    extern __shared__ float sm[];
    const uint32_t smb = smem_u32(sm);

    const int tid  = threadIdx.x;
    const int warp = tid >> 5;
    const int lane = tid & 31;
    const int g = lane >> 2;
    const int t = lane & 3;
    const int qt = blockIdx.x;              // 0..15, 128 rows each
    const int b  = blockIdx.y >> 4;
    const int h  = blockIdx.y & 15;
    const int len = g_len[b];

    const float* qb = qkv + (size_t)b * TT * H3 + h * HD;
    const float* kb = qb + HH;
    const float* vb = qb + 2 * HH;

    // ---- stage Q (128x64) into sm[0..8704) and LDSM to registers ----
    {
        const int r  = tid >> 1;
        const int dq = (tid & 1) * 32;
        const float* qp = qb + (size_t)(qt * 128 + r) * H3 + dq;
        #pragma unroll
        for (int j = 0; j < 8; j++) {
            float4 q4 = *(const float4*)(qp + j * 4);
            uint4 u = { f2tf32(q4.x), f2tf32(q4.y), f2tf32(q4.z), f2tf32(q4.w) };
            *(uint4*)&sm[r * 68 + dq + j * 4] = u;
        }
    }
    __syncthreads();

    const int arow   = (lane & 7) + ((lane >> 3) & 1) * 8;
    const int ahalf  = (lane >> 4) * 16;
    const int brow_i = (lane & 7) + (lane >> 4) * 8;
    const int bhalf  = ((lane >> 3) & 1) * 16;

    unsigned qf[8][4];
    {
        const uint32_t abase = smb + (warp * 16 + arow) * 272 + ahalf;
        #pragma unroll
        for (int ks = 0; ks < 8; ks++)
            LDSM4(qf[ks][0], qf[ks][1], qf[ks][2], qf[ks][3], abase + ks * 32);
    }
    __syncthreads();   // Q regs loaded; staging region reused for K below

    // per-lane softmax state (rows g and g+8 of this warp's 16)
    float m0 = -1e30f, m1 = -1e30f, l0 = 0.f, l1 = 0.f;
    float o[8][4];
    #pragma unroll
    for (int nt = 0; nt < 8; nt++)
        #pragma unroll
        for (int q = 0; q < 4; q++) o[nt][q] = 0.f;

    const int row0 = qt * 128 + warp * 16 + g;   // lane rows: row0, row0+8
    const int kt_max = min(2 * qt + 1, (len - 1) >> 6);

    // K/V loader mapping (R5-proven): 16 threads/row, 4 rows/thread
    const int rr = tid >> 4;
    const int d0 = (tid & 15) * 4;

    float4 kreg[4], vreg[4];
    #pragma unroll
    for (int it = 0; it < 4; it++) {
        const int c = rr + it * 16;
        kreg[it] = *(const float4*)(kb + (size_t)c * H3 + d0);
        vreg[it] = *(const float4*)(vb + (size_t)c * H3 + d0);
    }

    for (int kt = 0; kt <= kt_max; kt++) {
        const int buf = kt & 1;
        float* Kb = sm + buf * 4352;
        float* Vb = sm + 8704 + buf * 4352;

        // commit prefetched K/V (uint4 STS, tf32-rounded)
        #pragma unroll
        for (int it = 0; it < 4; it++) {
            const int c = rr + it * 16;
            uint4 uk = { f2tf32(kreg[it].x), f2tf32(kreg[it].y),
                         f2tf32(kreg[it].z), f2tf32(kreg[it].w) };
            uint4 uv = { f2tf32(vreg[it].x), f2tf32(vreg[it].y),
                         f2tf32(vreg[it].z), f2tf32(vreg[it].w) };
            *(uint4*)&Kb[c * 68 + d0] = uk;
            *(uint4*)&Vb[c * 68 + d0] = uv;
        }
        __syncthreads();   // the ONLY block sync per kv-tile

        // prefetch next tile
        if (kt < kt_max) {
            #pragma unroll
            for (int it = 0; it < 4; it++) {
                const int c = (kt + 1) * 64 + rr + it * 16;
                kreg[it] = *(const float4*)(kb + (size_t)c * H3 + d0);
                vreg[it] = *(const float4*)(vb + (size_t)c * H3 + d0);
            }
        }

        // ---- S = Q @ K^T (Q in regs, K frags via LDSM) ----
        float s[8][4];
        #pragma unroll
        for (int nt = 0; nt < 8; nt++)
            #pragma unroll
            for (int q = 0; q < 4; q++) s[nt][q] = 0.f;

        const uint32_t kfb = smb + buf * 17408 + brow_i * 272 + bhalf;
        #pragma unroll
        for (int ks = 0; ks < 8; ks++) {
            unsigned bf[8][2];
            #pragma unroll
            for (int np = 0; np < 4; np++) {
                unsigned r0, r1, r2, r3;
                LDSM4(r0, r1, r2, r3, kfb + np * 16 * 272 + ks * 32);
                bf[np * 2][0] = r0;      bf[np * 2][1] = r1;
                bf[np * 2 + 1][0] = r2;  bf[np * 2 + 1][1] = r3;
            }
            #pragma unroll
            for (int nt = 0; nt < 8; nt++)
                mma_tf32(s[nt], qf[ks], bf[nt]);
        }

        // ---- scale + mask in registers ----
        #pragma unroll
        for (int nt = 0; nt < 8; nt++) {
            const int c0 = kt * 64 + nt * 8 + 2 * t;
            s[nt][0] = (c0     <= row0     && c0     < len) ? s[nt][0] * 0.125f : -1e30f;
            s[nt][1] = (c0 + 1 <= row0     && c0 + 1 < len) ? s[nt][1] * 0.125f : -1e30f;
            s[nt][2] = (c0     <= row0 + 8 && c0     < len) ? s[nt][2] * 0.125f : -1e30f;
            s[nt][3] = (c0 + 1 <= row0 + 8 && c0 + 1 < len) ? s[nt][3] * 0.125f : -1e30f;
        }

        // ---- online softmax, fully in registers (quad shuffles) ----
        float mx0 = -1e30f, mx1 = -1e30f;
        #pragma unroll
        for (int nt = 0; nt < 8; nt++) {
            mx0 = fmaxf(mx0, fmaxf(s[nt][0], s[nt][1]));
            mx1 = fmaxf(mx1, fmaxf(s[nt][2], s[nt][3]));
        }
        mx0 = fmaxf(mx0, __shfl_xor_sync(0xffffffffu, mx0, 1));
        mx0 = fmaxf(mx0, __shfl_xor_sync(0xffffffffu, mx0, 2));
        mx1 = fmaxf(mx1, __shfl_xor_sync(0xffffffffu, mx1, 1));
        mx1 = fmaxf(mx1, __shfl_xor_sync(0xffffffffu, mx1, 2));

        const float mn0 = fmaxf(m0, mx0);
        const float mn1 = fmaxf(m1, mx1);
        const float a0 = __expf(m0 - mn0);
        const float a1 = __expf(m1 - mn1);
        m0 = mn0; m1 = mn1;

        float sum0 = 0.f, sum1 = 0.f;
        #pragma unroll
        for (int nt = 0; nt < 8; nt++) {
            s[nt][0] = __expf(s[nt][0] - mn0);
            s[nt][1] = __expf(s[nt][1] - mn0);
            s[nt][2] = __expf(s[nt][2] - mn1);
            s[nt][3] = __expf(s[nt][3] - mn1);
            sum0 += s[nt][0] + s[nt][1];
            sum1 += s[nt][2] + s[nt][3];
        }
        sum0 += __shfl_xor_sync(0xffffffffu, sum0, 1);
        sum0 += __shfl_xor_sync(0xffffffffu, sum0, 2);
        sum1 += __shfl_xor_sync(0xffffffffu, sum1, 1);
        sum1 += __shfl_xor_sync(0xffffffffu, sum1, 2);
        l0 = l0 * a0 + sum0;
        l1 = l1 * a1 + sum1;

        #pragma unroll
        for (int nt = 0; nt < 8; nt++) {
            o[nt][0] *= a0; o[nt][1] *= a0;
            o[nt][2] *= a1; o[nt][3] *= a1;
        }

        // ---- P -> warp-private smem (tf32 bits) ----
        float* Pw = sm + 17408 + warp * 1088;   // 16 rows x 68
        #pragma unroll
        for (int nt = 0; nt < 8; nt++) {
            float2 p0 = { __uint_as_float(f2tf32(s[nt][0])),
                          __uint_as_float(f2tf32(s[nt][1])) };
            float2 p1 = { __uint_as_float(f2tf32(s[nt][2])),
                          __uint_as_float(f2tf32(s[nt][3])) };
            *(float2*)&Pw[g * 68 + nt * 8 + 2 * t]       = p0;
            *(float2*)&Pw[(g + 8) * 68 + nt * 8 + 2 * t] = p1;
        }
        __syncwarp();

        // ---- O += P @ V (P frags via LDSM, V frags via LDS, R5-proven map) ----
        const uint32_t pbase = smb + 69632 + warp * 4352 + arow * 272 + ahalf;
        const unsigned* Vu = (const unsigned*)Vb;
        #pragma unroll
        for (int ks = 0; ks < 8; ks++) {
            unsigned af[4];
            LDSM4(af[0], af[1], af[2], af[3], pbase + ks * 32);
            #pragma unroll
            for (int nt = 0; nt < 8; nt++) {
                const int c = nt * 8 + g;
                unsigned vf[2] = { Vu[(ks * 8 + t) * 68 + c],
                                   Vu[(ks * 8 + t + 4) * 68 + c] };
                mma_tf32(o[nt], af, vf);
            }
        }
    }

    // ---- epilogue: normalize, tf32-round, store (B,T,H) ----
    {
        const float inv0 = 1.f / l0;
        const float inv1 = 1.f / l1;
        float* ob = att + (size_t)b * TT * HH
                  + (size_t)(qt * 128 + warp * 16) * HH + h * HD;
        #pragma unroll
        for (int nt = 0; nt < 8; nt++) {
            const int c = nt * 8 + 2 * t;
            float2 v0 = { __uint_as_float(f2tf32(o[nt][0] * inv0)),
                          __uint_as_float(f2tf32(o[nt][1] * inv0)) };
            float2 v1 = { __uint_as_float(f2tf32(o[nt][2] * inv1)),
                          __uint_as_float(f2tf32(o[nt][3] * inv1)) };
            *(float2*)&ob[(size_t)g * HH + c]       = v0;
            *(float2*)&ob[(size_t)(g + 8) * HH + c] = v1;
        }
    }
}

// ---------------------------------------------------------------------------

extern "C" void kernel_launch(void* const* d_in, const int* in_sizes, int n_in,
                              void* d_out, int out_size)
{
    const float*         inp   = (const float*)d_in[0];
    const unsigned char* mask  = (const unsigned char*)d_in[1];
    const float*         w_qkv = (const float*)d_in[2];
    const float*         b_qkv = (const float*)d_in[3];
    const float*         w_out = (const float*)d_in[4];
    const float*         b_out = (const float*)d_in[5];
    float*               out   = (float*)d_out;

    float *qkv_p, *att_p, *xr_p, *wqT_p, *woT_p;
    cudaGetSymbolAddress((void**)&qkv_p, g_qkv);
    cudaGetSymbolAddress((void**)&att_p, g_att);
    cudaGetSymbolAddress((void**)&xr_p,  g_xr);
    cudaGetSymbolAddress((void**)&wqT_p, g_wqT);
    cudaGetSymbolAddress((void**)&woT_p, g_woT);

    cudaFuncSetAttribute(attn_fa,
                         cudaFuncAttributeMaxDynamicSharedMemorySize, AT_SMEM);
    cudaFuncSetAttribute(tgemm_ldsm,
                         cudaFuncAttributeMaxDynamicSharedMemorySize, TG_SMEM);

    len_kernel<<<BB, 256>>>(mask);
    cvt_pre<<<512, 256>>>((const float4*)inp, (float4*)xr_p,
                          (BB * TT * HH) / 4);
    transpose_w<<<dim3(H3 / 32, HH / 32), dim3(32, 8)>>>(w_qkv, wqT_p, HH, H3);
    transpose_w<<<dim3(HH / 32, HH / 32), dim3(32, 8)>>>(w_out, woT_p, HH, HH);

    tgemm_ldsm<<<dim3(H3 / 128, (BB * TT) / 128), 256, TG_SMEM>>>(
        xr_p, wqT_p, b_qkv, qkv_p, BB * TT, H3, HH);
    attn_fa<<<dim3(TT / 128, BB * NH), 256, AT_SMEM>>>(qkv_p, att_p);
    tgemm_ldsm<<<dim3(HH / 128, (BB * TT) / 128), 256, TG_SMEM>>>(
        att_p, woT_p, b_out, out, BB * TT, HH, HH);
}

// round 11
// speedup vs baseline: 2.6066x; 1.9617x over previous
#include <cuda_runtime.h>
#include <cuda_fp16.h>
#include <math.h>
#include <stdint.h>

#define BB 4
#define TT 2048
#define HH 1024
#define NH 16
#define HD 64
#define H3 3072

// Scratch (allocation-free rule: __device__ globals)
__device__ __half g_qkv[(size_t)BB * TT * H3];  // (B,T,3H) fp16
__device__ __half g_att[(size_t)BB * TT * HH];  // (B,T,H)  fp16
__device__ __half g_xr [(size_t)BB * TT * HH];  // input fp16
__device__ __half g_wqT[(size_t)H3 * HH];       // w_qkv^T (3H,H) fp16
__device__ __half g_woT[(size_t)HH * HH];       // w_out^T (H,H) fp16
__device__ int    g_len[BB];

// ---------------------------------------------------------------------------
// helpers
// ---------------------------------------------------------------------------
__device__ __forceinline__ void mma_f16(
    float* d, const unsigned* a, const unsigned* b)
{
    asm volatile(
        "mma.sync.aligned.m16n8k16.row.col.f32.f16.f16.f32 "
        "{%0,%1,%2,%3}, {%4,%5,%6,%7}, {%8,%9}, {%0,%1,%2,%3};\n"
        : "+f"(d[0]), "+f"(d[1]), "+f"(d[2]), "+f"(d[3])
        : "r"(a[0]), "r"(a[1]), "r"(a[2]), "r"(a[3]),
          "r"(b[0]), "r"(b[1]));
}

__device__ __forceinline__ uint32_t smem_u32(const void* p) {
    uint32_t a;
    asm("{ .reg .u64 t; cvta.to.shared.u64 t, %1; cvt.u32.u64 %0, t; }"
        : "=r"(a) : "l"(p));
    return a;
}

__device__ __forceinline__ unsigned packh2(float a, float b) {
    __half2 h = __floats2half2_rn(a, b);
    return *(unsigned*)&h;
}

#define CP16(dst, src) \
    asm volatile("cp.async.ca.shared.global [%0], [%1], 16;" \
                 :: "r"(dst), "l"(src) : "memory")
#define CPCOMMIT() asm volatile("cp.async.commit_group;" ::: "memory")

#define LDSM4(r0, r1, r2, r3, addr) \
    asm volatile("ldmatrix.sync.aligned.m8n8.x4.shared.b16 {%0,%1,%2,%3}, [%4];" \
                 : "=r"(r0), "=r"(r1), "=r"(r2), "=r"(r3) : "r"(addr))

#define LDSM4T(r0, r1, r2, r3, addr) \
    asm volatile("ldmatrix.sync.aligned.m8n8.x4.trans.shared.b16 {%0,%1,%2,%3}, [%4];" \
                 : "=r"(r0), "=r"(r1), "=r"(r2), "=r"(r3) : "r"(addr))

// SW128 swizzle on 16B granules within a 128B row
#define SWR(row, byteoff) (((row) * 128 + (byteoff)) ^ (((row) & 7) << 4))

// ---------------------------------------------------------------------------
// Per-batch valid-prefix length; mask dtype sniffed from first 4 bytes.
// ---------------------------------------------------------------------------
__global__ void len_kernel(const unsigned char* __restrict__ mask) {
    __shared__ int sred[256];
    const unsigned int w0 = *(const unsigned int*)mask;
    const int b = blockIdx.x;
    int cnt = 0;
    if (w0 == 0x01010101u) {
        for (int t = threadIdx.x; t < TT; t += 256)
            cnt += (mask[(size_t)b * TT + t] != 0) ? 1 : 0;
    } else if (w0 == 0x3F800000u) {
        const float* m = (const float*)mask;
        for (int t = threadIdx.x; t < TT; t += 256)
            cnt += (m[(size_t)b * TT + t] != 0.f) ? 1 : 0;
    } else {
        const int* m = (const int*)mask;
        for (int t = threadIdx.x; t < TT; t += 256)
            cnt += (m[(size_t)b * TT + t] != 0) ? 1 : 0;
    }
    sred[threadIdx.x] = cnt;
    __syncthreads();
    for (int s = 128; s > 0; s >>= 1) {
        if (threadIdx.x < s) sred[threadIdx.x] += sred[threadIdx.x + s];
        __syncthreads();
    }
    if (threadIdx.x == 0) g_len[b] = sred[0];
}

// ---------------------------------------------------------------------------
// fp32 -> fp16 round (prepass)
// ---------------------------------------------------------------------------
__global__ void cvt_f2h(const float4* __restrict__ in, uint2* __restrict__ out,
                        int n4)
{
    for (int i = blockIdx.x * blockDim.x + threadIdx.x; i < n4;
         i += gridDim.x * blockDim.x) {
        float4 v = in[i];
        out[i] = make_uint2(packh2(v.x, v.y), packh2(v.z, v.w));
    }
}

// ---------------------------------------------------------------------------
// Weight transpose + fp16 round: D(C,R) = h(S(R,C)^T)
// ---------------------------------------------------------------------------
__global__ void transpose_w(const float* __restrict__ S, __half* __restrict__ D,
                            int R, int C)
{
    __shared__ float t[32][33];
    const int x = blockIdx.x * 32 + threadIdx.x;
    const int y0 = blockIdx.y * 32;
    #pragma unroll
    for (int i = threadIdx.y; i < 32; i += 8)
        t[i][threadIdx.x] = S[(size_t)(y0 + i) * C + x];
    __syncthreads();
    const int xo = y0 + threadIdx.x;
    const int yo0 = blockIdx.x * 32;
    #pragma unroll
    for (int i = threadIdx.y; i < 32; i += 8)
        D[(size_t)(yo0 + i) * R + xo] = __float2half_rn(t[threadIdx.x][i]);
}

// ---------------------------------------------------------------------------
// fp16 HMMA GEMM: cp.async + SW128 swizzle + ldmatrix, m16n8k16.
// C(M,N) = A(M,K) @ Bt(N,K)^T + bias(N).  CTA 128x128, K-chunk 64 halves
// (128B rows), 2 stages, 8 warps (2x4), warp tile 64x32.
// HOUT: write half C; else float C.
// ---------------------------------------------------------------------------
#define TG_STAGE 16384
#define TG_SMEM  (4 * TG_STAGE)   // A0 A1 B0 B1

template <bool HOUT>
__global__ __launch_bounds__(256) void hgemm(
    const __half* __restrict__ A, const __half* __restrict__ Bt,
    const float* __restrict__ bias, void* __restrict__ Cv,
    int M, int N, int K)
{
    extern __shared__ char smem[];
    const uint32_t sA0 = smem_u32(smem);
    const uint32_t sB0 = sA0 + 2 * TG_STAGE;

    const int tid   = threadIdx.x;
    const int warp  = tid >> 5;
    const int lane  = tid & 31;
    const int g     = lane >> 2;
    const int t     = lane & 3;
    const int warpM = warp & 1;
    const int warpN = warp >> 1;
    const int brow  = blockIdx.y * 128;
    const int bcol  = blockIdx.x * 128;

    // loader: row tid/2, granules (tid&1)*4 + q  (granule = 16B = 8 halves)
    const int lrow = tid >> 1;
    const int lg   = (tid & 1) * 4;
    const __half* Ap = A  + (size_t)(brow + lrow) * K + lg * 8;
    const __half* Bp = Bt + (size_t)(bcol + lrow) * K + lg * 8;
    uint32_t stA[2][4], stB[2][4];
    #pragma unroll
    for (int q = 0; q < 4; q++) {
        const uint32_t sw = SWR(lrow, (lg + q) * 16);
        stA[0][q] = sA0 + sw;
        stA[1][q] = sA0 + TG_STAGE + sw;
        stB[0][q] = sB0 + sw;
        stB[1][q] = sB0 + TG_STAGE + sw;
    }

    // consumer lane maps
    const int arow16 = lane & 15;               // A: 16x16 frags
    const int acol16 = (lane >> 4) * 16;
    const int brow_i = (lane & 7) + (lane >> 4) * 8;   // B: n16 x k16 frags
    const int bcol_i = ((lane >> 3) & 1) * 16;

    float acc[4][4][4];
    #pragma unroll
    for (int i = 0; i < 4; i++)
        #pragma unroll
        for (int j = 0; j < 4; j++)
            #pragma unroll
            for (int q = 0; q < 4; q++) acc[i][j][q] = 0.f;

    const int nch = K >> 6;   // 64-half chunks

    #pragma unroll
    for (int q = 0; q < 4; q++) {
        CP16(stA[0][q], Ap + q * 8);
        CP16(stB[0][q], Bp + q * 8);
    }
    CPCOMMIT();

    for (int kc = 0; kc < nch; kc++) {
        const int st = kc & 1;

        if (kc + 1 < nch) {
            const int sn = st ^ 1;
            const __half* Ap2 = Ap + (kc + 1) * 64;
            const __half* Bp2 = Bp + (kc + 1) * 64;
            #pragma unroll
            for (int q = 0; q < 4; q++) {
                CP16(stA[sn][q], Ap2 + q * 8);
                CP16(stB[sn][q], Bp2 + q * 8);
            }
            CPCOMMIT();
            asm volatile("cp.async.wait_group 1;" ::: "memory");
        } else {
            asm volatile("cp.async.wait_group 0;" ::: "memory");
        }
        __syncthreads();

        const uint32_t aBase = sA0 + st * TG_STAGE;
        const uint32_t bBase = sB0 + st * TG_STAGE;

        #pragma unroll
        for (int ks = 0; ks < 4; ks++) {
            const int kb = ks * 32;   // k16 sub-chunk = 32 bytes
            unsigned af[4][4];
            #pragma unroll
            for (int mt = 0; mt < 4; mt++) {
                const int r = warpM * 64 + mt * 16 + arow16;
                LDSM4(af[mt][0], af[mt][1], af[mt][2], af[mt][3],
                      aBase + SWR(r, kb + acol16));
            }
            unsigned bf[4][2];
            #pragma unroll
            for (int np = 0; np < 2; np++) {
                const int r = warpN * 32 + np * 16 + brow_i;
                unsigned r0, r1, r2, r3;
                LDSM4(r0, r1, r2, r3, bBase + SWR(r, kb + bcol_i));
                bf[np * 2][0] = r0;      bf[np * 2][1] = r1;
                bf[np * 2 + 1][0] = r2;  bf[np * 2 + 1][1] = r3;
            }
            #pragma unroll
            for (int mt = 0; mt < 4; mt++)
                #pragma unroll
                for (int nt = 0; nt < 4; nt++)
                    mma_f16(acc[mt][nt], af[mt], bf[nt]);
        }
        __syncthreads();
    }

    // epilogue: bias + store
    #pragma unroll
    for (int mt = 0; mt < 4; mt++) {
        const int r0 = brow + warpM * 64 + mt * 16 + g;
        #pragma unroll
        for (int nt = 0; nt < 4; nt++) {
            const int c = bcol + warpN * 32 + nt * 8 + 2 * t;
            const float bv0 = bias[c], bv1 = bias[c + 1];
            if (HOUT) {
                __half* C = (__half*)Cv;
                *(unsigned*)&C[(size_t)r0 * N + c] =
                    packh2(acc[mt][nt][0] + bv0, acc[mt][nt][1] + bv1);
                *(unsigned*)&C[(size_t)(r0 + 8) * N + c] =
                    packh2(acc[mt][nt][2] + bv0, acc[mt][nt][3] + bv1);
            } else {
                float* C = (float*)Cv;
                float2 v0 = {acc[mt][nt][0] + bv0, acc[mt][nt][1] + bv1};
                float2 v1 = {acc[mt][nt][2] + bv0, acc[mt][nt][3] + bv1};
                *(float2*)&C[(size_t)r0 * N + c]       = v0;
                *(float2*)&C[(size_t)(r0 + 8) * N + c] = v1;
            }
        }
    }
}

// ---------------------------------------------------------------------------
// FA2 fp16 attention: CTA = 128 q-rows x (b,h); warp owns 16 rows.
// Q frags in regs; K/V double-buffered (1 sync per kv-tile); register softmax;
// P via warp-private smem + LDSM; V B-frags via ldmatrix.trans.
// Smem bytes: K0 0, K1 8192, V0 16384, V1 24576, P 32768 + warp*2048.
// Q staging overlaps [0, 16384) (consumed before first K commit).
// ---------------------------------------------------------------------------
#define AT_SMEM 49152

__global__ __launch_bounds__(256) void attn_h(
    const __half* __restrict__ qkv, __half* __restrict__ att)
{
    extern __shared__ char sm[];
    const uint32_t smb = smem_u32(sm);

    const int tid  = threadIdx.x;
    const int warp = tid >> 5;
    const int lane = tid & 31;
    const int g = lane >> 2;
    const int t = lane & 3;
    const int qt = blockIdx.x;              // 0..15 (128 rows each)
    const int b  = blockIdx.y >> 4;
    const int h  = blockIdx.y & 15;
    const int len = g_len[b];

    const __half* qb = qkv + (size_t)b * TT * H3 + h * HD;
    const __half* kb = qb + HH;
    const __half* vb = qb + 2 * HH;

    // ---- stage Q (128 rows x 64 halves = 128B rows) ----
    {
        const int r = tid >> 1;
        #pragma unroll
        for (int q = 0; q < 4; q++) {
            const int gq = (tid & 1) * 4 + q;
            uint4 v = *(const uint4*)(qb + (size_t)(qt * 128 + r) * H3 + gq * 8);
            *(uint4*)(sm + SWR(r, gq * 16)) = v;
        }
    }
    __syncthreads();

    const int arow16 = lane & 15;
    const int acol16 = (lane >> 4) * 16;
    const int brow_i = (lane & 7) + (lane >> 4) * 8;
    const int bcol_i = ((lane >> 3) & 1) * 16;

    unsigned qf[4][4];
    #pragma unroll
    for (int ks = 0; ks < 4; ks++)
        LDSM4(qf[ks][0], qf[ks][1], qf[ks][2], qf[ks][3],
              smb + SWR(warp * 16 + arow16, ks * 32 + acol16));
    __syncthreads();   // Q staging region now reusable (K buffers)

    float m0 = -1e30f, m1 = -1e30f, l0 = 0.f, l1 = 0.f;
    float o[8][4];
    #pragma unroll
    for (int nt = 0; nt < 8; nt++)
        #pragma unroll
        for (int q = 0; q < 4; q++) o[nt][q] = 0.f;

    const int row0 = qt * 128 + warp * 16 + g;
    const int kt_max = min(2 * qt + 1, (len - 1) >> 6);

    // K/V loader: row tid/4 (0..63), granules (tid&3)*2 + {0,1}
    const int rv  = tid >> 2;
    const int gk0 = (tid & 3) * 2;

    uint4 kreg[2], vreg[2];
    #pragma unroll
    for (int j = 0; j < 2; j++) {
        kreg[j] = *(const uint4*)(kb + (size_t)rv * H3 + (gk0 + j) * 8);
        vreg[j] = *(const uint4*)(vb + (size_t)rv * H3 + (gk0 + j) * 8);
    }

    for (int kt = 0; kt <= kt_max; kt++) {
        const int buf = kt & 1;
        const uint32_t kbuf = smb + buf * 8192;
        const uint32_t vbuf = smb + 16384 + buf * 8192;

        #pragma unroll
        for (int j = 0; j < 2; j++) {
            *(uint4*)(sm + buf * 8192 + SWR(rv, (gk0 + j) * 16)) = kreg[j];
            *(uint4*)(sm + 16384 + buf * 8192 + SWR(rv, (gk0 + j) * 16)) = vreg[j];
        }
        __syncthreads();   // the ONLY block sync per kv-tile

        if (kt < kt_max) {
            #pragma unroll
            for (int j = 0; j < 2; j++) {
                const size_t ro = (size_t)((kt + 1) * 64 + rv) * H3 + (gk0 + j) * 8;
                kreg[j] = *(const uint4*)(kb + ro);
                vreg[j] = *(const uint4*)(vb + ro);
            }
        }

        // ---- S = Q @ K^T ----
        float s[8][4];
        #pragma unroll
        for (int nt = 0; nt < 8; nt++)
            #pragma unroll
            for (int q = 0; q < 4; q++) s[nt][q] = 0.f;

        #pragma unroll
        for (int ks = 0; ks < 4; ks++) {
            unsigned bf[8][2];
            #pragma unroll
            for (int np = 0; np < 4; np++) {
                unsigned r0, r1, r2, r3;
                LDSM4(r0, r1, r2, r3,
                      kbuf + SWR(np * 16 + brow_i, ks * 32 + bcol_i));
                bf[np * 2][0] = r0;      bf[np * 2][1] = r1;
                bf[np * 2 + 1][0] = r2;  bf[np * 2 + 1][1] = r3;
            }
            #pragma unroll
            for (int nt = 0; nt < 8; nt++)
                mma_f16(s[nt], qf[ks], bf[nt]);
        }

        // ---- scale + mask ----
        #pragma unroll
        for (int nt = 0; nt < 8; nt++) {
            const int c0 = kt * 64 + nt * 8 + 2 * t;
            s[nt][0] = (c0     <= row0     && c0     < len) ? s[nt][0] * 0.125f : -1e30f;
            s[nt][1] = (c0 + 1 <= row0     && c0 + 1 < len) ? s[nt][1] * 0.125f : -1e30f;
            s[nt][2] = (c0     <= row0 + 8 && c0     < len) ? s[nt][2] * 0.125f : -1e30f;
            s[nt][3] = (c0 + 1 <= row0 + 8 && c0 + 1 < len) ? s[nt][3] * 0.125f : -1e30f;
        }

        // ---- register online softmax (quad shuffles) ----
        float mx0 = -1e30f, mx1 = -1e30f;
        #pragma unroll
        for (int nt = 0; nt < 8; nt++) {
            mx0 = fmaxf(mx0, fmaxf(s[nt][0], s[nt][1]));
            mx1 = fmaxf(mx1, fmaxf(s[nt][2], s[nt][3]));
        }
        mx0 = fmaxf(mx0, __shfl_xor_sync(0xffffffffu, mx0, 1));
        mx0 = fmaxf(mx0, __shfl_xor_sync(0xffffffffu, mx0, 2));
        mx1 = fmaxf(mx1, __shfl_xor_sync(0xffffffffu, mx1, 1));
        mx1 = fmaxf(mx1, __shfl_xor_sync(0xffffffffu, mx1, 2));

        const float mn0 = fmaxf(m0, mx0);
        const float mn1 = fmaxf(m1, mx1);
        const float a0 = __expf(m0 - mn0);
        const float a1 = __expf(m1 - mn1);
        m0 = mn0; m1 = mn1;

        float sum0 = 0.f, sum1 = 0.f;
        #pragma unroll
        for (int nt = 0; nt < 8; nt++) {
            s[nt][0] = __expf(s[nt][0] - mn0);
            s[nt][1] = __expf(s[nt][1] - mn0);
            s[nt][2] = __expf(s[nt][2] - mn1);
            s[nt][3] = __expf(s[nt][3] - mn1);
            sum0 += s[nt][0] + s[nt][1];
            sum1 += s[nt][2] + s[nt][3];
        }
        sum0 += __shfl_xor_sync(0xffffffffu, sum0, 1);
        sum0 += __shfl_xor_sync(0xffffffffu, sum0, 2);
        sum1 += __shfl_xor_sync(0xffffffffu, sum1, 1);
        sum1 += __shfl_xor_sync(0xffffffffu, sum1, 2);
        l0 = l0 * a0 + sum0;
        l1 = l1 * a1 + sum1;

        #pragma unroll
        for (int nt = 0; nt < 8; nt++) {
            o[nt][0] *= a0; o[nt][1] *= a0;
            o[nt][2] *= a1; o[nt][3] *= a1;
        }

        // ---- P -> warp-private smem (half, 16 rows x 64 halves) ----
        const int pOff = 32768 + warp * 2048;
        #pragma unroll
        for (int nt = 0; nt < 8; nt++) {
            *(unsigned*)(sm + pOff + SWR(g,     nt * 16 + 4 * t)) =
                packh2(s[nt][0], s[nt][1]);
            *(unsigned*)(sm + pOff + SWR(g + 8, nt * 16 + 4 * t)) =
                packh2(s[nt][2], s[nt][3]);
        }
        __syncwarp();

        // ---- O += P @ V ----
        const uint32_t pB = smb + pOff;
        #pragma unroll
        for (int ks = 0; ks < 4; ks++) {
            unsigned pf[4];
            LDSM4(pf[0], pf[1], pf[2], pf[3],
                  pB + SWR(arow16, ks * 32 + acol16));
            unsigned vf[8][2];
            #pragma unroll
            for (int np = 0; np < 4; np++) {
                unsigned r0, r1, r2, r3;
                LDSM4T(r0, r1, r2, r3,
                       vbuf + SWR(ks * 16 + ((lane >> 3) & 1) * 8 + (lane & 7),
                                  np * 32 + (lane >> 4) * 16));
                vf[np * 2][0] = r0;      vf[np * 2][1] = r1;
                vf[np * 2 + 1][0] = r2;  vf[np * 2 + 1][1] = r3;
            }
            #pragma unroll
            for (int nt = 0; nt < 8; nt++)
                mma_f16(o[nt], pf, vf[nt]);
        }
    }

    // ---- epilogue: normalize, store half (B,T,H) ----
    {
        const float inv0 = 1.f / l0;
        const float inv1 = 1.f / l1;
        __half* ob = att + (size_t)b * TT * HH
                   + (size_t)(qt * 128 + warp * 16) * HH + h * HD;
        #pragma unroll
        for (int nt = 0; nt < 8; nt++) {
            const int c = nt * 8 + 2 * t;
            *(unsigned*)&ob[(size_t)g * HH + c] =
                packh2(o[nt][0] * inv0, o[nt][1] * inv0);
            *(unsigned*)&ob[(size_t)(g + 8) * HH + c] =
                packh2(o[nt][2] * inv1, o[nt][3] * inv1);
        }
    }
}

// ---------------------------------------------------------------------------

extern "C" void kernel_launch(void* const* d_in, const int* in_sizes, int n_in,
                              void* d_out, int out_size)
{
    const float*         inp   = (const float*)d_in[0];
    const unsigned char* mask  = (const unsigned char*)d_in[1];
    const float*         w_qkv = (const float*)d_in[2];
    const float*         b_qkv = (const float*)d_in[3];
    const float*         w_out = (const float*)d_in[4];
    const float*         b_out = (const float*)d_in[5];
    float*               out   = (float*)d_out;

    __half *qkv_p, *att_p, *xr_p, *wqT_p, *woT_p;
    cudaGetSymbolAddress((void**)&qkv_p, g_qkv);
    cudaGetSymbolAddress((void**)&att_p, g_att);
    cudaGetSymbolAddress((void**)&xr_p,  g_xr);
    cudaGetSymbolAddress((void**)&wqT_p, g_wqT);
    cudaGetSymbolAddress((void**)&woT_p, g_woT);

    cudaFuncSetAttribute(attn_h,
                         cudaFuncAttributeMaxDynamicSharedMemorySize, AT_SMEM);
    cudaFuncSetAttribute(hgemm<true>,
                         cudaFuncAttributeMaxDynamicSharedMemorySize, TG_SMEM);
    cudaFuncSetAttribute(hgemm<false>,
                         cudaFuncAttributeMaxDynamicSharedMemorySize, TG_SMEM);

    len_kernel<<<BB, 256>>>(mask);
    cvt_f2h<<<512, 256>>>((const float4*)inp, (uint2*)xr_p,
                          (BB * TT * HH) / 4);
    transpose_w<<<dim3(H3 / 32, HH / 32), dim3(32, 8)>>>(w_qkv, wqT_p, HH, H3);
    transpose_w<<<dim3(HH / 32, HH / 32), dim3(32, 8)>>>(w_out, woT_p, HH, HH);

    hgemm<true><<<dim3(H3 / 128, (BB * TT) / 128), 256, TG_SMEM>>>(
        xr_p, wqT_p, b_qkv, qkv_p, BB * TT, H3, HH);
    attn_h<<<dim3(TT / 128, BB * NH), 256, AT_SMEM>>>(qkv_p, att_p);
    hgemm<false><<<dim3(HH / 128, (BB * TT) / 128), 256, TG_SMEM>>>(
        att_p, woT_p, b_out, out, BB * TT, HH, HH);
}